// round 10
// baseline (speedup 1.0000x reference)
#include <cuda_runtime.h>
#include <cuda_bf16.h>
#include <cstdint>

#define BATCH 2
#define SEQ   1024
#define HS    768
#define NH    12
#define HD    64
#define WIN   64
#define HALF  32
#define MTOK  (BATCH*SEQ)   // 2048
#define NX    (MTOK*HS)
#define NW    (HS*HS)
#define BK    32
#define NKC   (HS / BK)     // 24

// ---------------------------------------------------------------------------
// Device-global scratch
// ---------------------------------------------------------------------------
__device__ float g_q[NX];
__device__ float g_k[NX];
__device__ float g_v[NX];
__device__ __nv_bfloat16 g_xhi[NX], g_xlo[NX];
__device__ __nv_bfloat16 g_chi[NX], g_clo[NX];
__device__ __nv_bfloat16 g_wqhi[NW], g_wqlo[NW];
__device__ __nv_bfloat16 g_wkhi[NW], g_wklo[NW];
__device__ __nv_bfloat16 g_wvhi[NW], g_wvlo[NW];
__device__ __nv_bfloat16 g_wohi[NW], g_wolo[NW];

// ---------------------------------------------------------------------------
// PTX helpers
// ---------------------------------------------------------------------------
__device__ __forceinline__ uint32_t smem_u32(const void* p) {
    uint32_t a;
    asm("{ .reg .u64 t; cvta.to.shared.u64 t, %1; cvt.u32.u64 %0, t; }" : "=r"(a) : "l"(p));
    return a;
}
__device__ __forceinline__ void cp16(uint32_t dst, const void* src) {
    asm volatile("cp.async.cg.shared.global [%0], [%1], 16;" :: "r"(dst), "l"(src));
}
#define CP_COMMIT() asm volatile("cp.async.commit_group;")
#define CP_WAIT0()  asm volatile("cp.async.wait_group 0;")
#define CP_WAIT1()  asm volatile("cp.async.wait_group 1;")

__device__ __forceinline__ void ldsm4(uint32_t* r, uint32_t addr) {
    asm volatile("ldmatrix.sync.aligned.m8n8.x4.shared.b16 {%0,%1,%2,%3}, [%4];"
        : "=r"(r[0]), "=r"(r[1]), "=r"(r[2]), "=r"(r[3]) : "r"(addr));
}
__device__ __forceinline__ void mma_bf16(float* d, const uint32_t* a, uint32_t b0, uint32_t b1) {
    asm volatile(
        "mma.sync.aligned.m16n8k16.row.col.f32.bf16.bf16.f32 "
        "{%0,%1,%2,%3}, {%4,%5,%6,%7}, {%8,%9}, {%0,%1,%2,%3};"
        : "+f"(d[0]), "+f"(d[1]), "+f"(d[2]), "+f"(d[3])
        : "r"(a[0]), "r"(a[1]), "r"(a[2]), "r"(a[3]), "r"(b0), "r"(b1));
}

// ===========================================================================
// QKV GEMM: CTA 128x128, 4 warps (2M x 2N), warp tile 64x64, 2 CTAs/SM.
// smem/stage: Ahi(128r) Alo(128r) Bhi(128r) Blo(128r), row 64B padded 80B.
//   Ahi@0  Alo@10240  Bhi@20480  Blo@30720   stage = 40960 B, 2 stages.
// Grid (6,16,3) = 288 ~ one full wave at 2 CTAs/SM.
// ===========================================================================
#define QSTG  40960
#define SMEM_QKV (2 * QSTG)

__device__ __forceinline__ void load_q(
    uint32_t sb, int st, int kc,
    const __nv_bfloat16* __restrict__ Bh, const __nv_bfloat16* __restrict__ Bl,
    int by, int bx, int tid)
{
    const int k0 = kc * BK;
    const uint32_t base = sb + (uint32_t)st * QSTG;
    #pragma unroll
    for (int it = 0; it < 16; it++) {
        int idx = it * 128 + tid;          // 0..2047
        int r   = idx >> 2;                // 0..511
        int cb  = idx & 3;
        const __nv_bfloat16* src; uint32_t toff; int row;
        if (r < 128)      { src = g_xhi + (size_t)(by * 128 + r) * HS;       toff = 0;     row = r; }
        else if (r < 256) { src = g_xlo + (size_t)(by * 128 + (r - 128)) * HS; toff = 10240; row = r - 128; }
        else if (r < 384) { src = Bh   + (size_t)(bx * 128 + (r - 256)) * HS; toff = 20480; row = r - 256; }
        else              { src = Bl   + (size_t)(bx * 128 + (r - 384)) * HS; toff = 30720; row = r - 384; }
        cp16(base + toff + (uint32_t)row * 80 + (uint32_t)cb * 16, src + k0 + cb * 8);
    }
}

__global__ __launch_bounds__(128, 2) void qkv_kernel(
    const float* __restrict__ bq, const float* __restrict__ bk, const float* __restrict__ bv)
{
    const __nv_bfloat16 *Bh, *Bl; const float* bias; float* C;
    if (blockIdx.z == 0)      { Bh = g_wqhi; Bl = g_wqlo; bias = bq; C = g_q; }
    else if (blockIdx.z == 1) { Bh = g_wkhi; Bl = g_wklo; bias = bk; C = g_k; }
    else                      { Bh = g_wvhi; Bl = g_wvlo; bias = bv; C = g_v; }

    extern __shared__ char smem[];
    const uint32_t sb = smem_u32(smem);
    const int tid  = threadIdx.x;
    const int lane = tid & 31;
    const int warp = tid >> 5;
    const int wm   = warp & 1;          // 0..1 -> M*64
    const int wn   = warp >> 1;         // 0..1 -> N*64
    const int bx = blockIdx.x, by = blockIdx.y;

    float acc[4][8][4];
    #pragma unroll
    for (int i = 0; i < 4; i++)
        #pragma unroll
        for (int j = 0; j < 8; j++)
            #pragma unroll
            for (int r = 0; r < 4; r++) acc[i][j][r] = 0.f;

    load_q(sb, 0, 0, Bh, Bl, by, bx, tid); CP_COMMIT();
    load_q(sb, 1, 1, Bh, Bl, by, bx, tid); CP_COMMIT();

    const uint32_t arow = (uint32_t)(lane & 15);
    const uint32_t asel = (uint32_t)(lane >> 4) * 16;

    for (int kc = 0; kc < NKC; kc++) {
        if (kc + 1 < NKC) { CP_WAIT1(); } else { CP_WAIT0(); }
        __syncthreads();
        const uint32_t base = sb + (uint32_t)(kc & 1) * QSTG;

        #pragma unroll
        for (int ks = 0; ks < 2; ks++) {
            const uint32_t colb = (uint32_t)ks * 32 + asel;
            uint32_t ah[4][4], al[4][4];
            #pragma unroll
            for (int i = 0; i < 4; i++) {
                uint32_t ro = (uint32_t)(wm * 64 + i * 16) + arow;
                ldsm4(ah[i], base +         ro * 80 + colb);
                ldsm4(al[i], base + 10240 + ro * 80 + colb);
            }
            #pragma unroll
            for (int jj = 0; jj < 4; jj++) {
                uint32_t bhf[4], blf[4];
                uint32_t ro = (uint32_t)(wn * 64 + jj * 16) + arow;
                ldsm4(bhf, base + 20480 + ro * 80 + colb);
                ldsm4(blf, base + 30720 + ro * 80 + colb);
                #pragma unroll
                for (int i = 0; i < 4; i++) {            // hi*hi
                    mma_bf16(acc[i][jj * 2 + 0], ah[i], bhf[0], bhf[2]);
                    mma_bf16(acc[i][jj * 2 + 1], ah[i], bhf[1], bhf[3]);
                }
                #pragma unroll
                for (int i = 0; i < 4; i++) {            // hi*lo
                    mma_bf16(acc[i][jj * 2 + 0], ah[i], blf[0], blf[2]);
                    mma_bf16(acc[i][jj * 2 + 1], ah[i], blf[1], blf[3]);
                }
                #pragma unroll
                for (int i = 0; i < 4; i++) {            // lo*hi
                    mma_bf16(acc[i][jj * 2 + 0], al[i], bhf[0], bhf[2]);
                    mma_bf16(acc[i][jj * 2 + 1], al[i], bhf[1], bhf[3]);
                }
            }
        }
        __syncthreads();
        if (kc + 2 < NKC) {
            load_q(sb, kc & 1, kc + 2, Bh, Bl, by, bx, tid);
            CP_COMMIT();
        }
    }

    const int g  = lane >> 2;
    const int tg = lane & 3;
    #pragma unroll
    for (int i = 0; i < 4; i++) {
        const int row = by * 128 + wm * 64 + i * 16 + g;
        #pragma unroll
        for (int jj = 0; jj < 4; jj++) {
            #pragma unroll
            for (int s = 0; s < 2; s++) {
                const int col = bx * 128 + wn * 64 + jj * 16 + s * 8 + tg * 2;
                const float* a = acc[i][jj * 2 + s];
                const float b0 = bias[col], b1 = bias[col + 1];
                *(float2*)&C[(size_t)row * HS + col]       = make_float2(a[0] + b0, a[1] + b1);
                *(float2*)&C[(size_t)(row + 8) * HS + col] = make_float2(a[2] + b0, a[3] + b1);
            }
        }
    }
}

// ===========================================================================
// Output projection: CTA 64x128, 4 warps (2M x 2N), warp tile 32x64.
// smem/stage: Ahi(64) Alo(64) Bhi(128) Blo(128) rows * 80B = 30720 B, 3 st.
//   Ahi@0  Alo@5120  Bhi@10240  Blo@20480.  Grid (6,32) = 192, 2 CTAs/SM.
// ===========================================================================
#define OSTG  30720
#define SMEM_OUT (3 * OSTG)

__device__ __forceinline__ void load_o(
    uint32_t sb, int st, int kc, int by, int bx, int tid)
{
    const int k0 = kc * BK;
    const uint32_t base = sb + (uint32_t)st * OSTG;
    #pragma unroll
    for (int it = 0; it < 12; it++) {
        int idx = it * 128 + tid;          // 0..1535
        int r   = idx >> 2;                // 0..383
        int cb  = idx & 3;
        const __nv_bfloat16* src; uint32_t toff; int row;
        if (r < 64)       { src = g_chi  + (size_t)(by * 64 + r) * HS;          toff = 0;     row = r; }
        else if (r < 128) { src = g_clo  + (size_t)(by * 64 + (r - 64)) * HS;   toff = 5120;  row = r - 64; }
        else if (r < 256) { src = g_wohi + (size_t)(bx * 128 + (r - 128)) * HS; toff = 10240; row = r - 128; }
        else              { src = g_wolo + (size_t)(bx * 128 + (r - 256)) * HS; toff = 20480; row = r - 256; }
        cp16(base + toff + (uint32_t)row * 80 + (uint32_t)cb * 16, src + k0 + cb * 8);
    }
}

__global__ __launch_bounds__(128, 2) void out_kernel(
    const float* __restrict__ bo, float* __restrict__ Cout)
{
    extern __shared__ char smem[];
    const uint32_t sb = smem_u32(smem);
    const int tid  = threadIdx.x;
    const int lane = tid & 31;
    const int warp = tid >> 5;
    const int wm   = warp & 1;          // 0..1 -> M*32
    const int wn   = warp >> 1;         // 0..1 -> N*64
    const int bx = blockIdx.x, by = blockIdx.y;

    float acc[2][8][4];
    #pragma unroll
    for (int i = 0; i < 2; i++)
        #pragma unroll
        for (int j = 0; j < 8; j++)
            #pragma unroll
            for (int r = 0; r < 4; r++) acc[i][j][r] = 0.f;

    load_o(sb, 0, 0, by, bx, tid); CP_COMMIT();
    load_o(sb, 1, 1, by, bx, tid); CP_COMMIT();

    const uint32_t arow = (uint32_t)(lane & 15);
    const uint32_t asel = (uint32_t)(lane >> 4) * 16;

    for (int kc = 0; kc < NKC; kc++) {
        if (kc + 1 < NKC) { CP_WAIT1(); } else { CP_WAIT0(); }
        __syncthreads();
        if (kc + 2 < NKC) {
            load_o(sb, (kc + 2) % 3, kc + 2, by, bx, tid);
            CP_COMMIT();
        }
        const uint32_t base = sb + (uint32_t)(kc % 3) * OSTG;

        #pragma unroll
        for (int ks = 0; ks < 2; ks++) {
            const uint32_t colb = (uint32_t)ks * 32 + asel;
            uint32_t ah[2][4], al[2][4];
            #pragma unroll
            for (int i = 0; i < 2; i++) {
                uint32_t ro = (uint32_t)(wm * 32 + i * 16) + arow;
                ldsm4(ah[i], base +        ro * 80 + colb);
                ldsm4(al[i], base + 5120 + ro * 80 + colb);
            }
            #pragma unroll
            for (int jj = 0; jj < 4; jj++) {
                uint32_t bhf[4], blf[4];
                uint32_t ro = (uint32_t)(wn * 64 + jj * 16) + arow;
                ldsm4(bhf, base + 10240 + ro * 80 + colb);
                ldsm4(blf, base + 20480 + ro * 80 + colb);
                #pragma unroll
                for (int i = 0; i < 2; i++) {
                    mma_bf16(acc[i][jj * 2 + 0], ah[i], bhf[0], bhf[2]);
                    mma_bf16(acc[i][jj * 2 + 1], ah[i], bhf[1], bhf[3]);
                }
                #pragma unroll
                for (int i = 0; i < 2; i++) {
                    mma_bf16(acc[i][jj * 2 + 0], ah[i], blf[0], blf[2]);
                    mma_bf16(acc[i][jj * 2 + 1], ah[i], blf[1], blf[3]);
                }
                #pragma unroll
                for (int i = 0; i < 2; i++) {
                    mma_bf16(acc[i][jj * 2 + 0], al[i], bhf[0], bhf[2]);
                    mma_bf16(acc[i][jj * 2 + 1], al[i], bhf[1], bhf[3]);
                }
            }
        }
        __syncthreads();
    }

    const int g  = lane >> 2;
    const int tg = lane & 3;
    #pragma unroll
    for (int i = 0; i < 2; i++) {
        const int row = by * 64 + wm * 32 + i * 16 + g;
        #pragma unroll
        for (int jj = 0; jj < 4; jj++) {
            #pragma unroll
            for (int s = 0; s < 2; s++) {
                const int col = bx * 128 + wn * 64 + jj * 16 + s * 8 + tg * 2;
                const float* a = acc[i][jj * 2 + s];
                const float b0 = bo[col], b1 = bo[col + 1];
                *(float2*)&Cout[(size_t)row * HS + col]       = make_float2(a[0] + b0, a[1] + b1);
                *(float2*)&Cout[(size_t)(row + 8) * HS + col] = make_float2(a[2] + b0, a[3] + b1);
            }
        }
    }
}

// ---------------------------------------------------------------------------
// Split fp32 -> bf16 hi/lo (X + 4 weights).
// ---------------------------------------------------------------------------
__global__ void split_kernel(
    const float* __restrict__ X,
    const float* __restrict__ Wq, const float* __restrict__ Wk,
    const float* __restrict__ Wv, const float* __restrict__ Wo)
{
    const int tot4 = (NX + 4 * NW) / 4;
    for (int i4 = blockIdx.x * blockDim.x + threadIdx.x; i4 < tot4; i4 += gridDim.x * blockDim.x) {
        int i = i4 * 4;
        const float* src; __nv_bfloat16 *hi, *lo; int r;
        if (i < NX) { src = X; hi = g_xhi; lo = g_xlo; r = i; }
        else {
            int j = i - NX; int w = j / NW; r = j - w * NW;
            if (w == 0)      { src = Wq; hi = g_wqhi; lo = g_wqlo; }
            else if (w == 1) { src = Wk; hi = g_wkhi; lo = g_wklo; }
            else if (w == 2) { src = Wv; hi = g_wvhi; lo = g_wvlo; }
            else             { src = Wo; hi = g_wohi; lo = g_wolo; }
        }
        float4 x = *(const float4*)(src + r);
        float xs[4] = {x.x, x.y, x.z, x.w};
        __nv_bfloat162 h2[2], l2[2];
        #pragma unroll
        for (int t = 0; t < 4; t++) {
            __nv_bfloat16 h = __float2bfloat16(xs[t]);
            ((__nv_bfloat16*)h2)[t] = h;
            ((__nv_bfloat16*)l2)[t] = __float2bfloat16(xs[t] - __bfloat162float(h));
        }
        *(__nv_bfloat162*)(hi + r)     = h2[0];
        *(__nv_bfloat162*)(hi + r + 2) = h2[1];
        *(__nv_bfloat162*)(lo + r)     = l2[0];
        *(__nv_bfloat162*)(lo + r + 2) = l2[1];
    }
}

// ---------------------------------------------------------------------------
// Sliding-window attention: 64 queries/block, 1024 threads, 2 queries/warp.
// Staged rows s0-32 .. s0+94 (127), stride 68 (conflict-free).
// Exact zero-padding semantics; per-query math identical to proven version.
// ---------------------------------------------------------------------------
#define AR2 127
#define KST 68
#define SMEM_ATTN ((2*AR2*KST + 64*64) * 4)

__global__ __launch_bounds__(1024) void attn_kernel()
{
    extern __shared__ float sm[];
    float (*Ks)[KST] = (float(*)[KST])sm;
    float (*Vs)[KST] = (float(*)[KST])(sm + AR2 * KST);
    float (*Ps)[64]  = (float(*)[64])(sm + 2 * AR2 * KST);

    const int s0 = blockIdx.x * 64;
    const int h  = blockIdx.y;
    const int b  = blockIdx.z;
    const int tid = threadIdx.x;
    const int base = (b * SEQ) * HS + h * HD;

    for (int i = tid; i < AR2 * 16; i += 1024) {
        int r = i >> 4, c4 = (i & 15) * 4;
        int j = s0 - HALF + r;
        float4 kv = make_float4(0.f, 0.f, 0.f, 0.f), vv = kv;
        if (j >= 0 && j < SEQ) {
            int off = base + j * HS + c4;
            kv = *(const float4*)&g_k[off];
            vv = *(const float4*)&g_v[off];
        }
        *(float4*)&Ks[r][c4] = kv;
        *(float4*)&Vs[r][c4] = vv;
    }
    __syncthreads();

    const int wq   = tid >> 5;
    const int lane = tid & 31;

    #pragma unroll
    for (int qs = 0; qs < 2; qs++) {
        const int q = wq + qs * 32;
        const float* qrow = g_q + base + (s0 + q) * HS;

        float sc0 = 0.f, sc1 = 0.f;
        #pragma unroll
        for (int d4 = 0; d4 < 16; d4++) {
            float4 qv = __ldg((const float4*)(qrow + d4 * 4));
            float4 k0 = *(const float4*)&Ks[q + lane][d4 * 4];
            float4 k1 = *(const float4*)&Ks[q + lane + 32][d4 * 4];
            sc0 += qv.x * k0.x + qv.y * k0.y + qv.z * k0.z + qv.w * k0.w;
            sc1 += qv.x * k1.x + qv.y * k1.y + qv.z * k1.z + qv.w * k1.w;
        }
        sc0 *= 0.125f;
        sc1 *= 0.125f;

        float m = fmaxf(sc0, sc1);
        #pragma unroll
        for (int o = 16; o; o >>= 1) m = fmaxf(m, __shfl_xor_sync(0xFFFFFFFFu, m, o));
        float e0 = __expf(sc0 - m);
        float e1 = __expf(sc1 - m);
        float sum = e0 + e1;
        #pragma unroll
        for (int o = 16; o; o >>= 1) sum += __shfl_xor_sync(0xFFFFFFFFu, sum, o);
        float inv = 1.f / sum;
        Ps[q][lane]      = e0 * inv;
        Ps[q][lane + 32] = e1 * inv;
    }
    __syncwarp();

    #pragma unroll
    for (int qs = 0; qs < 2; qs++) {
        const int q = wq + qs * 32;
        float c0 = 0.f, c1 = 0.f;
        #pragma unroll
        for (int w = 0; w < 64; w++) {
            float p = Ps[q][w];
            float2 v = *(const float2*)&Vs[q + w][2 * lane];
            c0 += p * v.x;
            c1 += p * v.y;
        }
        const int orow = base + (s0 + q) * HS + 2 * lane;
        __nv_bfloat162 hi2, lo2;
        hi2.x = __float2bfloat16(c0);
        hi2.y = __float2bfloat16(c1);
        lo2.x = __float2bfloat16(c0 - __bfloat162float(hi2.x));
        lo2.y = __float2bfloat16(c1 - __bfloat162float(hi2.y));
        *(__nv_bfloat162*)&g_chi[orow] = hi2;
        *(__nv_bfloat162*)&g_clo[orow] = lo2;
    }
}

// ---------------------------------------------------------------------------
extern "C" void kernel_launch(void* const* d_in, const int* in_sizes, int n_in,
                              void* d_out, int out_size)
{
    const float* X  = (const float*)d_in[0];
    const float* Wq = (const float*)d_in[1];
    const float* bq = (const float*)d_in[2];
    const float* Wk = (const float*)d_in[3];
    const float* bk = (const float*)d_in[4];
    const float* Wv = (const float*)d_in[5];
    const float* bv = (const float*)d_in[6];
    const float* Wo = (const float*)d_in[7];
    const float* bo = (const float*)d_in[8];
    float* out = (float*)d_out;

    static bool attr_done = false;
    if (!attr_done) {
        cudaFuncSetAttribute(qkv_kernel,  cudaFuncAttributeMaxDynamicSharedMemorySize, SMEM_QKV);
        cudaFuncSetAttribute(out_kernel,  cudaFuncAttributeMaxDynamicSharedMemorySize, SMEM_OUT);
        cudaFuncSetAttribute(attn_kernel, cudaFuncAttributeMaxDynamicSharedMemorySize, SMEM_ATTN);
        attr_done = true;
    }

    split_kernel<<<1024, 256>>>(X, Wq, Wk, Wv, Wo);

    dim3 qkv_grid(HS / 128, MTOK / 128, 3);    // (6, 16, 3) = 288 ~ one wave @2/SM
    qkv_kernel<<<qkv_grid, 128, SMEM_QKV>>>(bq, bk, bv);

    dim3 attn_grid(SEQ / 64, NH, BATCH);       // (16, 12, 2) = 384
    attn_kernel<<<attn_grid, 1024, SMEM_ATTN>>>();

    dim3 out_grid(HS / 128, MTOK / 64, 1);     // (6, 32) = 192
    out_kernel<<<out_grid, 128, SMEM_OUT>>>(bo, out);
}

// round 11
// speedup vs baseline: 1.6900x; 1.6900x over previous
#include <cuda_runtime.h>
#include <cuda_fp16.h>
#include <cstdint>

#define BATCH 2
#define SEQ   1024
#define HS    768
#define NH    12
#define HD    64
#define WIN   64
#define HALF  32
#define MTOK  (BATCH*SEQ)   // 2048
#define NX    (MTOK*HS)
#define NW    (HS*HS)
#define BK    32
#define NKC   (HS / BK)     // 24

// ---------------------------------------------------------------------------
// Device-global scratch
// ---------------------------------------------------------------------------
__device__ float g_q[NX];
__device__ float g_k[NX];
__device__ float g_v[NX];
__device__ __half g_xh[NX];
__device__ __half g_ch[NX];
__device__ __half g_wqh[NW], g_wkh[NW], g_wvh[NW], g_woh[NW];

// ---------------------------------------------------------------------------
// PTX helpers
// ---------------------------------------------------------------------------
__device__ __forceinline__ uint32_t smem_u32(const void* p) {
    uint32_t a;
    asm("{ .reg .u64 t; cvta.to.shared.u64 t, %1; cvt.u32.u64 %0, t; }" : "=r"(a) : "l"(p));
    return a;
}
__device__ __forceinline__ void cp16(uint32_t dst, const void* src) {
    asm volatile("cp.async.cg.shared.global [%0], [%1], 16;" :: "r"(dst), "l"(src));
}
#define CP_COMMIT() asm volatile("cp.async.commit_group;")
#define CP_WAIT0()  asm volatile("cp.async.wait_group 0;")
#define CP_WAIT1()  asm volatile("cp.async.wait_group 1;")

__device__ __forceinline__ void ldsm4(uint32_t* r, uint32_t addr) {
    asm volatile("ldmatrix.sync.aligned.m8n8.x4.shared.b16 {%0,%1,%2,%3}, [%4];"
        : "=r"(r[0]), "=r"(r[1]), "=r"(r[2]), "=r"(r[3]) : "r"(addr));
}
__device__ __forceinline__ void mma_f16(float* d, const uint32_t* a, uint32_t b0, uint32_t b1) {
    asm volatile(
        "mma.sync.aligned.m16n8k16.row.col.f32.f16.f16.f32 "
        "{%0,%1,%2,%3}, {%4,%5,%6,%7}, {%8,%9}, {%0,%1,%2,%3};"
        : "+f"(d[0]), "+f"(d[1]), "+f"(d[2]), "+f"(d[3])
        : "r"(a[0]), "r"(a[1]), "r"(a[2]), "r"(a[3]), "r"(b0), "r"(b1));
}

// ===========================================================================
// QKV GEMM (fp16 single pass): CTA 128x256, 8 warps (2M x 4N), warp 64x64.
// smem/stage: A(128 rows)+B(256 rows), row 64B padded 80B = 30720 B, 3 st.
//   A@0  B@10240.  Grid (3,16,3) = 144 ~ one wave, 1 CTA/SM.
// ===========================================================================
#define QSTG  30720
#define SMEM_QKV (3 * QSTG)

__device__ __forceinline__ void load_q(
    uint32_t sb, int st, int kc, const __half* __restrict__ W,
    int by, int bx, int tid)
{
    const int k0 = kc * BK;
    const uint32_t base = sb + (uint32_t)st * QSTG;
    #pragma unroll
    for (int it = 0; it < 6; it++) {
        int idx = it * 256 + tid;          // 0..1535
        int r   = idx >> 2;                // 0..383
        int cb  = idx & 3;
        const __half* src; uint32_t toff; int row;
        if (r < 128) { src = g_xh + (size_t)(by * 128 + r) * HS;        toff = 0;     row = r; }
        else         { src = W    + (size_t)(bx * 256 + (r - 128)) * HS; toff = 10240; row = r - 128; }
        cp16(base + toff + (uint32_t)row * 80 + (uint32_t)cb * 16, src + k0 + cb * 8);
    }
}

__global__ __launch_bounds__(256, 1) void qkv_kernel(
    const float* __restrict__ bq, const float* __restrict__ bk, const float* __restrict__ bv)
{
    const __half* W; const float* bias; float* C;
    if (blockIdx.z == 0)      { W = g_wqh; bias = bq; C = g_q; }
    else if (blockIdx.z == 1) { W = g_wkh; bias = bk; C = g_k; }
    else                      { W = g_wvh; bias = bv; C = g_v; }

    extern __shared__ char smem[];
    const uint32_t sb = smem_u32(smem);
    const int tid  = threadIdx.x;
    const int lane = tid & 31;
    const int warp = tid >> 5;
    const int wm   = warp & 1;          // 0..1 -> M*64
    const int wn   = warp >> 1;         // 0..3 -> N*64
    const int bx = blockIdx.x, by = blockIdx.y;

    float acc[4][8][4];
    #pragma unroll
    for (int i = 0; i < 4; i++)
        #pragma unroll
        for (int j = 0; j < 8; j++)
            #pragma unroll
            for (int r = 0; r < 4; r++) acc[i][j][r] = 0.f;

    load_q(sb, 0, 0, W, by, bx, tid); CP_COMMIT();
    load_q(sb, 1, 1, W, by, bx, tid); CP_COMMIT();

    const uint32_t arow = (uint32_t)(lane & 15);
    const uint32_t asel = (uint32_t)(lane >> 4) * 16;

    for (int kc = 0; kc < NKC; kc++) {
        if (kc + 1 < NKC) { CP_WAIT1(); } else { CP_WAIT0(); }
        __syncthreads();
        if (kc + 2 < NKC) {
            load_q(sb, (kc + 2) % 3, kc + 2, W, by, bx, tid);
            CP_COMMIT();
        }
        const uint32_t base = sb + (uint32_t)(kc % 3) * QSTG;

        #pragma unroll
        for (int ks = 0; ks < 2; ks++) {
            const uint32_t colb = (uint32_t)ks * 32 + asel;
            uint32_t ah[4][4];
            #pragma unroll
            for (int i = 0; i < 4; i++) {
                uint32_t ro = (uint32_t)(wm * 64 + i * 16) + arow;
                ldsm4(ah[i], base + ro * 80 + colb);
            }
            #pragma unroll
            for (int jj = 0; jj < 4; jj++) {
                uint32_t bf[4];
                uint32_t ro = (uint32_t)(wn * 64 + jj * 16) + arow;
                ldsm4(bf, base + 10240 + ro * 80 + colb);
                #pragma unroll
                for (int i = 0; i < 4; i++) {
                    mma_f16(acc[i][jj * 2 + 0], ah[i], bf[0], bf[2]);
                    mma_f16(acc[i][jj * 2 + 1], ah[i], bf[1], bf[3]);
                }
            }
        }
        __syncthreads();
    }

    const int g  = lane >> 2;
    const int tg = lane & 3;
    #pragma unroll
    for (int i = 0; i < 4; i++) {
        const int row = by * 128 + wm * 64 + i * 16 + g;
        #pragma unroll
        for (int jj = 0; jj < 4; jj++) {
            #pragma unroll
            for (int s = 0; s < 2; s++) {
                const int col = bx * 256 + wn * 64 + jj * 16 + s * 8 + tg * 2;
                const float* a = acc[i][jj * 2 + s];
                const float b0 = bias[col], b1 = bias[col + 1];
                *(float2*)&C[(size_t)row * HS + col]       = make_float2(a[0] + b0, a[1] + b1);
                *(float2*)&C[(size_t)(row + 8) * HS + col] = make_float2(a[2] + b0, a[3] + b1);
            }
        }
    }
}

// ===========================================================================
// Output projection (fp16 single pass): CTA 64x96, 6 warps (2M x 3N),
// warp 32x32, 3 CTAs/SM.  smem/stage: A(64)+B(96) rows*80B = 12800 B, 3 st.
//   A@0  B@5120.  Grid (8,32) = 256, single resident wave.
// ===========================================================================
#define OSTG  12800
#define SMEM_OUT (3 * OSTG)

__device__ __forceinline__ void load_o(
    uint32_t sb, int st, int kc, int by, int bx, int tid)
{
    const int k0 = kc * BK;
    const uint32_t base = sb + (uint32_t)st * OSTG;
    #pragma unroll
    for (int it = 0; it < 4; it++) {
        int idx = it * 192 + tid;          // 0..767, valid < 640
        if (idx < 640) {
            int r  = idx >> 2;             // 0..159
            int cb = idx & 3;
            const __half* src; uint32_t toff; int row;
            if (r < 64) { src = g_ch  + (size_t)(by * 64 + r) * HS;        toff = 0;    row = r; }
            else        { src = g_woh + (size_t)(bx * 96 + (r - 64)) * HS; toff = 5120; row = r - 64; }
            cp16(base + toff + (uint32_t)row * 80 + (uint32_t)cb * 16, src + k0 + cb * 8);
        }
    }
}

__global__ __launch_bounds__(192, 3) void out_kernel(
    const float* __restrict__ bo, float* __restrict__ Cout)
{
    extern __shared__ char smem[];
    const uint32_t sb = smem_u32(smem);
    const int tid  = threadIdx.x;
    const int lane = tid & 31;
    const int warp = tid >> 5;
    const int wm   = warp & 1;          // 0..1 -> M*32
    const int wn   = warp >> 1;         // 0..2 -> N*32
    const int bx = blockIdx.x, by = blockIdx.y;

    float acc[2][4][4];
    #pragma unroll
    for (int i = 0; i < 2; i++)
        #pragma unroll
        for (int j = 0; j < 4; j++)
            #pragma unroll
            for (int r = 0; r < 4; r++) acc[i][j][r] = 0.f;

    load_o(sb, 0, 0, by, bx, tid); CP_COMMIT();
    load_o(sb, 1, 1, by, bx, tid); CP_COMMIT();

    const uint32_t arow = (uint32_t)(lane & 15);
    const uint32_t asel = (uint32_t)(lane >> 4) * 16;

    for (int kc = 0; kc < NKC; kc++) {
        if (kc + 1 < NKC) { CP_WAIT1(); } else { CP_WAIT0(); }
        __syncthreads();
        if (kc + 2 < NKC) {
            load_o(sb, (kc + 2) % 3, kc + 2, by, bx, tid);
            CP_COMMIT();
        }
        const uint32_t base = sb + (uint32_t)(kc % 3) * OSTG;

        #pragma unroll
        for (int ks = 0; ks < 2; ks++) {
            const uint32_t colb = (uint32_t)ks * 32 + asel;
            uint32_t ah[2][4];
            #pragma unroll
            for (int i = 0; i < 2; i++) {
                uint32_t ro = (uint32_t)(wm * 32 + i * 16) + arow;
                ldsm4(ah[i], base + ro * 80 + colb);
            }
            #pragma unroll
            for (int jj = 0; jj < 2; jj++) {
                uint32_t bf[4];
                uint32_t ro = (uint32_t)(wn * 32 + jj * 16) + arow;
                ldsm4(bf, base + 5120 + ro * 80 + colb);
                #pragma unroll
                for (int i = 0; i < 2; i++) {
                    mma_f16(acc[i][jj * 2 + 0], ah[i], bf[0], bf[2]);
                    mma_f16(acc[i][jj * 2 + 1], ah[i], bf[1], bf[3]);
                }
            }
        }
        __syncthreads();
    }

    const int g  = lane >> 2;
    const int tg = lane & 3;
    #pragma unroll
    for (int i = 0; i < 2; i++) {
        const int row = by * 64 + wm * 32 + i * 16 + g;
        #pragma unroll
        for (int j = 0; j < 4; j++) {
            const int col = bx * 96 + wn * 32 + (j >> 1) * 16 + (j & 1) * 8 + tg * 2;
            const float b0 = bo[col], b1 = bo[col + 1];
            *(float2*)&Cout[(size_t)row * HS + col] =
                make_float2(acc[i][j][0] + b0, acc[i][j][1] + b1);
            *(float2*)&Cout[(size_t)(row + 8) * HS + col] =
                make_float2(acc[i][j][2] + b0, acc[i][j][3] + b1);
        }
    }
}

// ---------------------------------------------------------------------------
// Convert fp32 -> fp16 (X + 4 weights).
// ---------------------------------------------------------------------------
__global__ void cvt_kernel(
    const float* __restrict__ X,
    const float* __restrict__ Wq, const float* __restrict__ Wk,
    const float* __restrict__ Wv, const float* __restrict__ Wo)
{
    const int tot4 = (NX + 4 * NW) / 4;
    for (int i4 = blockIdx.x * blockDim.x + threadIdx.x; i4 < tot4; i4 += gridDim.x * blockDim.x) {
        int i = i4 * 4;
        const float* src; __half* dst; int r;
        if (i < NX) { src = X; dst = g_xh; r = i; }
        else {
            int j = i - NX; int w = j / NW; r = j - w * NW;
            if (w == 0)      { src = Wq; dst = g_wqh; }
            else if (w == 1) { src = Wk; dst = g_wkh; }
            else if (w == 2) { src = Wv; dst = g_wvh; }
            else             { src = Wo; dst = g_woh; }
        }
        float4 x = *(const float4*)(src + r);
        __half2 h0 = __floats2half2_rn(x.x, x.y);
        __half2 h1 = __floats2half2_rn(x.z, x.w);
        *(__half2*)(dst + r)     = h0;
        *(__half2*)(dst + r + 2) = h1;
    }
}

// ---------------------------------------------------------------------------
// Sliding-window attention (fp32, proven). Writes ctx as fp16.
// ---------------------------------------------------------------------------
#define AR 95
#define KST 68
#define SMEM_ATTN ((2*AR*KST + 32*64) * 4)

__global__ __launch_bounds__(1024) void attn_kernel()
{
    extern __shared__ float sm[];
    float (*Ks)[KST] = (float(*)[KST])sm;
    float (*Vs)[KST] = (float(*)[KST])(sm + AR * KST);
    float (*Ps)[64]  = (float(*)[64])(sm + 2 * AR * KST);

    const int s0 = blockIdx.x * 32;
    const int h  = blockIdx.y;
    const int b  = blockIdx.z;
    const int tid = threadIdx.x;
    const int base = (b * SEQ) * HS + h * HD;

    for (int i = tid; i < AR * 16; i += 1024) {
        int r = i >> 4, c4 = (i & 15) * 4;
        int j = s0 - HALF + r;
        float4 kv = make_float4(0.f, 0.f, 0.f, 0.f), vv = kv;
        if (j >= 0 && j < SEQ) {
            int off = base + j * HS + c4;
            kv = *(const float4*)&g_k[off];
            vv = *(const float4*)&g_v[off];
        }
        *(float4*)&Ks[r][c4] = kv;
        *(float4*)&Vs[r][c4] = vv;
    }
    __syncthreads();

    const int wq   = tid >> 5;
    const int lane = tid & 31;
    const float* qrow = g_q + base + (s0 + wq) * HS;

    float sc0 = 0.f, sc1 = 0.f;
    #pragma unroll
    for (int d4 = 0; d4 < 16; d4++) {
        float4 q  = __ldg((const float4*)(qrow + d4 * 4));
        float4 k0 = *(const float4*)&Ks[wq + lane][d4 * 4];
        float4 k1 = *(const float4*)&Ks[wq + lane + 32][d4 * 4];
        sc0 += q.x * k0.x + q.y * k0.y + q.z * k0.z + q.w * k0.w;
        sc1 += q.x * k1.x + q.y * k1.y + q.z * k1.z + q.w * k1.w;
    }
    sc0 *= 0.125f;
    sc1 *= 0.125f;

    float m = fmaxf(sc0, sc1);
    #pragma unroll
    for (int o = 16; o; o >>= 1) m = fmaxf(m, __shfl_xor_sync(0xFFFFFFFFu, m, o));
    float e0 = __expf(sc0 - m);
    float e1 = __expf(sc1 - m);
    float sum = e0 + e1;
    #pragma unroll
    for (int o = 16; o; o >>= 1) sum += __shfl_xor_sync(0xFFFFFFFFu, sum, o);
    float inv = 1.f / sum;
    Ps[wq][lane]      = e0 * inv;
    Ps[wq][lane + 32] = e1 * inv;
    __syncwarp();

    float c0 = 0.f, c1 = 0.f;
    #pragma unroll
    for (int w = 0; w < 64; w++) {
        float p = Ps[wq][w];
        float2 v = *(const float2*)&Vs[wq + w][2 * lane];
        c0 += p * v.x;
        c1 += p * v.y;
    }
    const int orow = base + (s0 + wq) * HS + 2 * lane;
    *(__half2*)&g_ch[orow] = __floats2half2_rn(c0, c1);
}

// ---------------------------------------------------------------------------
extern "C" void kernel_launch(void* const* d_in, const int* in_sizes, int n_in,
                              void* d_out, int out_size)
{
    const float* X  = (const float*)d_in[0];
    const float* Wq = (const float*)d_in[1];
    const float* bq = (const float*)d_in[2];
    const float* Wk = (const float*)d_in[3];
    const float* bk = (const float*)d_in[4];
    const float* Wv = (const float*)d_in[5];
    const float* bv = (const float*)d_in[6];
    const float* Wo = (const float*)d_in[7];
    const float* bo = (const float*)d_in[8];
    float* out = (float*)d_out;

    static bool attr_done = false;
    if (!attr_done) {
        cudaFuncSetAttribute(qkv_kernel,  cudaFuncAttributeMaxDynamicSharedMemorySize, SMEM_QKV);
        cudaFuncSetAttribute(out_kernel,  cudaFuncAttributeMaxDynamicSharedMemorySize, SMEM_OUT);
        cudaFuncSetAttribute(attn_kernel, cudaFuncAttributeMaxDynamicSharedMemorySize, SMEM_ATTN);
        attr_done = true;
    }

    cvt_kernel<<<1024, 256>>>(X, Wq, Wk, Wv, Wo);

    dim3 qkv_grid(HS / 256, MTOK / 128, 3);    // (3, 16, 3) = 144 ~ one wave
    qkv_kernel<<<qkv_grid, 256, SMEM_QKV>>>(bq, bk, bv);

    dim3 attn_grid(SEQ / 32, NH, BATCH);       // (32, 12, 2)
    attn_kernel<<<attn_grid, 1024, SMEM_ATTN>>>();

    dim3 out_grid(HS / 96, MTOK / 64, 1);      // (8, 32) = 256, single wave
    out_kernel<<<out_grid, 192, SMEM_OUT>>>(bo, out);
}

// round 12
// speedup vs baseline: 2.4302x; 1.4380x over previous
#include <cuda_runtime.h>
#include <cuda_fp16.h>
#include <cstdint>

#define BATCH 2
#define SEQ   1024
#define HS    768
#define NH    12
#define HD    64
#define WIN   64
#define HALF  32
#define MTOK  (BATCH*SEQ)   // 2048
#define NX    (MTOK*HS)
#define NW    (HS*HS)
#define BK    32
#define NKC   (HS / BK)     // 24

// ---------------------------------------------------------------------------
// Device-global scratch
// ---------------------------------------------------------------------------
__device__ __half g_qh[NX], g_kh[NX], g_vh[NX];
__device__ __half g_xh[NX];
__device__ __half g_ch[NX];
__device__ __half g_wqh[NW], g_wkh[NW], g_wvh[NW], g_woh[NW];

// ---------------------------------------------------------------------------
// PTX helpers
// ---------------------------------------------------------------------------
__device__ __forceinline__ uint32_t smem_u32(const void* p) {
    uint32_t a;
    asm("{ .reg .u64 t; cvta.to.shared.u64 t, %1; cvt.u32.u64 %0, t; }" : "=r"(a) : "l"(p));
    return a;
}
__device__ __forceinline__ void cp16(uint32_t dst, const void* src) {
    asm volatile("cp.async.cg.shared.global [%0], [%1], 16;" :: "r"(dst), "l"(src));
}
#define CP_COMMIT() asm volatile("cp.async.commit_group;")
#define CP_WAIT0()  asm volatile("cp.async.wait_group 0;")
#define CP_WAIT1()  asm volatile("cp.async.wait_group 1;")

__device__ __forceinline__ void ldsm4(uint32_t* r, uint32_t addr) {
    asm volatile("ldmatrix.sync.aligned.m8n8.x4.shared.b16 {%0,%1,%2,%3}, [%4];"
        : "=r"(r[0]), "=r"(r[1]), "=r"(r[2]), "=r"(r[3]) : "r"(addr));
}
__device__ __forceinline__ void mma_f16(float* d, const uint32_t* a, uint32_t b0, uint32_t b1) {
    asm volatile(
        "mma.sync.aligned.m16n8k16.row.col.f32.f16.f16.f32 "
        "{%0,%1,%2,%3}, {%4,%5,%6,%7}, {%8,%9}, {%0,%1,%2,%3};"
        : "+f"(d[0]), "+f"(d[1]), "+f"(d[2]), "+f"(d[3])
        : "r"(a[0]), "r"(a[1]), "r"(a[2]), "r"(a[3]), "r"(b0), "r"(b1));
}

// ===========================================================================
// QKV GEMM (fp16): CTA 128x256, 8 warps (2M x 4N), warp 64x64, 1 CTA/SM.
// smem/stage: A(128 rows)+B(256 rows), row 64B padded 80B = 30720 B, 3 st.
// Writes q/k/v directly as fp16.
// ===========================================================================
#define QSTG  30720
#define SMEM_QKV (3 * QSTG)

__device__ __forceinline__ void load_q(
    uint32_t sb, int st, int kc, const __half* __restrict__ W,
    int by, int bx, int tid)
{
    const int k0 = kc * BK;
    const uint32_t base = sb + (uint32_t)st * QSTG;
    #pragma unroll
    for (int it = 0; it < 6; it++) {
        int idx = it * 256 + tid;
        int r   = idx >> 2;
        int cb  = idx & 3;
        const __half* src; uint32_t toff; int row;
        if (r < 128) { src = g_xh + (size_t)(by * 128 + r) * HS;         toff = 0;     row = r; }
        else         { src = W    + (size_t)(bx * 256 + (r - 128)) * HS; toff = 10240; row = r - 128; }
        cp16(base + toff + (uint32_t)row * 80 + (uint32_t)cb * 16, src + k0 + cb * 8);
    }
}

__global__ __launch_bounds__(256, 1) void qkv_kernel(
    const float* __restrict__ bq, const float* __restrict__ bk, const float* __restrict__ bv)
{
    const __half* W; const float* bias; __half* C;
    if (blockIdx.z == 0)      { W = g_wqh; bias = bq; C = g_qh; }
    else if (blockIdx.z == 1) { W = g_wkh; bias = bk; C = g_kh; }
    else                      { W = g_wvh; bias = bv; C = g_vh; }

    extern __shared__ char smem[];
    const uint32_t sb = smem_u32(smem);
    const int tid  = threadIdx.x;
    const int lane = tid & 31;
    const int warp = tid >> 5;
    const int wm   = warp & 1;
    const int wn   = warp >> 1;
    const int bx = blockIdx.x, by = blockIdx.y;

    float acc[4][8][4];
    #pragma unroll
    for (int i = 0; i < 4; i++)
        #pragma unroll
        for (int j = 0; j < 8; j++)
            #pragma unroll
            for (int r = 0; r < 4; r++) acc[i][j][r] = 0.f;

    load_q(sb, 0, 0, W, by, bx, tid); CP_COMMIT();
    load_q(sb, 1, 1, W, by, bx, tid); CP_COMMIT();

    const uint32_t arow = (uint32_t)(lane & 15);
    const uint32_t asel = (uint32_t)(lane >> 4) * 16;

    for (int kc = 0; kc < NKC; kc++) {
        if (kc + 1 < NKC) { CP_WAIT1(); } else { CP_WAIT0(); }
        __syncthreads();
        if (kc + 2 < NKC) {
            load_q(sb, (kc + 2) % 3, kc + 2, W, by, bx, tid);
            CP_COMMIT();
        }
        const uint32_t base = sb + (uint32_t)(kc % 3) * QSTG;

        #pragma unroll
        for (int ks = 0; ks < 2; ks++) {
            const uint32_t colb = (uint32_t)ks * 32 + asel;
            uint32_t ah[4][4];
            #pragma unroll
            for (int i = 0; i < 4; i++) {
                uint32_t ro = (uint32_t)(wm * 64 + i * 16) + arow;
                ldsm4(ah[i], base + ro * 80 + colb);
            }
            #pragma unroll
            for (int jj = 0; jj < 4; jj++) {
                uint32_t bf[4];
                uint32_t ro = (uint32_t)(wn * 64 + jj * 16) + arow;
                ldsm4(bf, base + 10240 + ro * 80 + colb);
                #pragma unroll
                for (int i = 0; i < 4; i++) {
                    mma_f16(acc[i][jj * 2 + 0], ah[i], bf[0], bf[2]);
                    mma_f16(acc[i][jj * 2 + 1], ah[i], bf[1], bf[3]);
                }
            }
        }
        __syncthreads();
    }

    const int g  = lane >> 2;
    const int tg = lane & 3;
    #pragma unroll
    for (int i = 0; i < 4; i++) {
        const int row = by * 128 + wm * 64 + i * 16 + g;
        #pragma unroll
        for (int jj = 0; jj < 4; jj++) {
            #pragma unroll
            for (int s = 0; s < 2; s++) {
                const int col = bx * 256 + wn * 64 + jj * 16 + s * 8 + tg * 2;
                const float* a = acc[i][jj * 2 + s];
                const float b0 = bias[col], b1 = bias[col + 1];
                *(__half2*)&C[(size_t)row * HS + col]       = __floats2half2_rn(a[0] + b0, a[1] + b1);
                *(__half2*)&C[(size_t)(row + 8) * HS + col] = __floats2half2_rn(a[2] + b0, a[3] + b1);
            }
        }
    }
}

// ===========================================================================
// Output projection (fp16): CTA 64x96, 6 warps (2M x 3N), warp 32x32, 3/SM.
// ===========================================================================
#define OSTG  12800
#define SMEM_OUT (3 * OSTG)

__device__ __forceinline__ void load_o(
    uint32_t sb, int st, int kc, int by, int bx, int tid)
{
    const int k0 = kc * BK;
    const uint32_t base = sb + (uint32_t)st * OSTG;
    #pragma unroll
    for (int it = 0; it < 4; it++) {
        int idx = it * 192 + tid;
        if (idx < 640) {
            int r  = idx >> 2;
            int cb = idx & 3;
            const __half* src; uint32_t toff; int row;
            if (r < 64) { src = g_ch  + (size_t)(by * 64 + r) * HS;        toff = 0;    row = r; }
            else        { src = g_woh + (size_t)(bx * 96 + (r - 64)) * HS; toff = 5120; row = r - 64; }
            cp16(base + toff + (uint32_t)row * 80 + (uint32_t)cb * 16, src + k0 + cb * 8);
        }
    }
}

__global__ __launch_bounds__(192, 3) void out_kernel(
    const float* __restrict__ bo, float* __restrict__ Cout)
{
    extern __shared__ char smem[];
    const uint32_t sb = smem_u32(smem);
    const int tid  = threadIdx.x;
    const int lane = tid & 31;
    const int warp = tid >> 5;
    const int wm   = warp & 1;
    const int wn   = warp >> 1;
    const int bx = blockIdx.x, by = blockIdx.y;

    float acc[2][4][4];
    #pragma unroll
    for (int i = 0; i < 2; i++)
        #pragma unroll
        for (int j = 0; j < 4; j++)
            #pragma unroll
            for (int r = 0; r < 4; r++) acc[i][j][r] = 0.f;

    load_o(sb, 0, 0, by, bx, tid); CP_COMMIT();
    load_o(sb, 1, 1, by, bx, tid); CP_COMMIT();

    const uint32_t arow = (uint32_t)(lane & 15);
    const uint32_t asel = (uint32_t)(lane >> 4) * 16;

    for (int kc = 0; kc < NKC; kc++) {
        if (kc + 1 < NKC) { CP_WAIT1(); } else { CP_WAIT0(); }
        __syncthreads();
        if (kc + 2 < NKC) {
            load_o(sb, (kc + 2) % 3, kc + 2, by, bx, tid);
            CP_COMMIT();
        }
        const uint32_t base = sb + (uint32_t)(kc % 3) * OSTG;

        #pragma unroll
        for (int ks = 0; ks < 2; ks++) {
            const uint32_t colb = (uint32_t)ks * 32 + asel;
            uint32_t ah[2][4];
            #pragma unroll
            for (int i = 0; i < 2; i++) {
                uint32_t ro = (uint32_t)(wm * 32 + i * 16) + arow;
                ldsm4(ah[i], base + ro * 80 + colb);
            }
            #pragma unroll
            for (int jj = 0; jj < 2; jj++) {
                uint32_t bf[4];
                uint32_t ro = (uint32_t)(wn * 32 + jj * 16) + arow;
                ldsm4(bf, base + 5120 + ro * 80 + colb);
                #pragma unroll
                for (int i = 0; i < 2; i++) {
                    mma_f16(acc[i][jj * 2 + 0], ah[i], bf[0], bf[2]);
                    mma_f16(acc[i][jj * 2 + 1], ah[i], bf[1], bf[3]);
                }
            }
        }
        __syncthreads();
    }

    const int g  = lane >> 2;
    const int tg = lane & 3;
    #pragma unroll
    for (int i = 0; i < 2; i++) {
        const int row = by * 64 + wm * 32 + i * 16 + g;
        #pragma unroll
        for (int j = 0; j < 4; j++) {
            const int col = bx * 96 + wn * 32 + (j >> 1) * 16 + (j & 1) * 8 + tg * 2;
            const float b0 = bo[col], b1 = bo[col + 1];
            *(float2*)&Cout[(size_t)row * HS + col] =
                make_float2(acc[i][j][0] + b0, acc[i][j][1] + b1);
            *(float2*)&Cout[(size_t)(row + 8) * HS + col] =
                make_float2(acc[i][j][2] + b0, acc[i][j][3] + b1);
        }
    }
}

// ---------------------------------------------------------------------------
// Convert fp32 -> fp16 (X + 4 weights).
// ---------------------------------------------------------------------------
__global__ void cvt_kernel(
    const float* __restrict__ X,
    const float* __restrict__ Wq, const float* __restrict__ Wk,
    const float* __restrict__ Wv, const float* __restrict__ Wo)
{
    const int tot4 = (NX + 4 * NW) / 4;
    for (int i4 = blockIdx.x * blockDim.x + threadIdx.x; i4 < tot4; i4 += gridDim.x * blockDim.x) {
        int i = i4 * 4;
        const float* src; __half* dst; int r;
        if (i < NX) { src = X; dst = g_xh; r = i; }
        else {
            int j = i - NX; int w = j / NW; r = j - w * NW;
            if (w == 0)      { src = Wq; dst = g_wqh; }
            else if (w == 1) { src = Wk; dst = g_wkh; }
            else if (w == 2) { src = Wv; dst = g_wvh; }
            else             { src = Wo; dst = g_woh; }
        }
        float4 x = *(const float4*)(src + r);
        *(__half2*)(dst + r)     = __floats2half2_rn(x.x, x.y);
        *(__half2*)(dst + r + 2) = __floats2half2_rn(x.z, x.w);
    }
}

// ===========================================================================
// Sliding-window attention via HMMA.
// Block = 32 queries of one (b,h); 384 threads (12 warps).
// Phase 1: scores(32x96) = Q(32x64) @ K^T(96 staged rows x 64) [fp16 in, fp32 out]
// Phase 2: banded fp32 softmax (query q uses score cols q..q+63)
// Phase 3: ctx(32x64) = P(32x96, fp16, zeros outside band) @ V^T
// Zero-padded OOB rows give score 0 / contribute 0 — exact reference semantics.
// smem: Qh[32][72]h @0, Kh[96][72]h @4608, Vt[64][104]h @18432,
//       Ss[32][100]f @31744, Ph[32][104]h @44544.  Total 51200 B.
// ===========================================================================
#define SMEM_ATTN 51200

__global__ __launch_bounds__(384) void attn_kernel()
{
    extern __shared__ char smc[];
    const uint32_t sb = smem_u32(smc);
    __half* Qh = (__half*)smc;              // stride 72 halfs (144B)
    __half* Kh = (__half*)(smc + 4608);     // stride 72
    __half* Vt = (__half*)(smc + 18432);    // stride 104 halfs (208B)
    float*  Ss = (float*)(smc + 31744);     // stride 100 floats (400B)
    __half* Ph = (__half*)(smc + 44544);    // stride 104

    const int s0 = blockIdx.x * 32;
    const int h  = blockIdx.y;
    const int b  = blockIdx.z;
    const int tid = threadIdx.x;
    const int base = (b * SEQ) * HS + h * HD;

    // Stage Q (32 rows x 8 16B-chunks)
    for (int i = tid; i < 256; i += 384) {
        int r = i >> 3, c = i & 7;
        *(uint4*)&Qh[r * 72 + c * 8] = *(const uint4*)&g_qh[base + (s0 + r) * HS + c * 8];
    }
    // Stage K (96 rows; row 95 and OOB zero)
    for (int i = tid; i < 768; i += 384) {
        int r = i >> 3, c = i & 7;
        int j = s0 - HALF + r;
        uint4 v = make_uint4(0u, 0u, 0u, 0u);
        if (r < 95 && j >= 0 && j < SEQ) v = *(const uint4*)&g_kh[base + j * HS + c * 8];
        *(uint4*)&Kh[r * 72 + c * 8] = v;
    }
    // Stage V transposed: Vt[dim][stagedRow]
    for (int i = tid; i < 768; i += 384) {
        int r = i >> 3, c = i & 7;
        int j = s0 - HALF + r;
        __half hv[8];
        uint4 v = make_uint4(0u, 0u, 0u, 0u);
        if (r < 95 && j >= 0 && j < SEQ) v = *(const uint4*)&g_vh[base + j * HS + c * 8];
        *(uint4*)hv = v;
        #pragma unroll
        for (int t = 0; t < 8; t++) Vt[(c * 8 + t) * 104 + r] = hv[t];
    }
    // Zero P (zeros outside the band must stay zero)
    for (int i = tid; i < 1664; i += 384) ((uint32_t*)Ph)[i] = 0u;
    __syncthreads();

    const int lane = tid & 31;
    const int warp = tid >> 5;
    const uint32_t arow = (uint32_t)(lane & 15);
    const uint32_t asel = (uint32_t)(lane >> 4) * 16;
    const uint32_t qb = sb;
    const uint32_t kb = sb + 4608;
    const uint32_t vb = sb + 18432;
    const uint32_t pb = sb + 44544;

    // Phase 1: scores. 12 warps = 2M x 6N (m16 x n16 tiles), K=64 (4 steps).
    {
        const int wm = warp & 1;
        const int wn = warp >> 1;       // 0..5
        float c0[4] = {0.f, 0.f, 0.f, 0.f};
        float c1[4] = {0.f, 0.f, 0.f, 0.f};
        #pragma unroll
        for (int ks = 0; ks < 4; ks++) {
            const uint32_t colb = (uint32_t)ks * 32 + asel;
            uint32_t a[4], bf[4];
            ldsm4(a,  qb + ((uint32_t)(wm * 16) + arow) * 144 + colb);
            ldsm4(bf, kb + ((uint32_t)(wn * 16) + arow) * 144 + colb);
            mma_f16(c0, a, bf[0], bf[2]);
            mma_f16(c1, a, bf[1], bf[3]);
        }
        const int g  = lane >> 2;
        const int tg = lane & 3;
        const int row = wm * 16 + g;
        const int col = wn * 16 + tg * 2;
        *(float2*)&Ss[row * 100 + col]           = make_float2(c0[0], c0[1]);
        *(float2*)&Ss[(row + 8) * 100 + col]     = make_float2(c0[2], c0[3]);
        *(float2*)&Ss[row * 100 + col + 8]       = make_float2(c1[0], c1[1]);
        *(float2*)&Ss[(row + 8) * 100 + col + 8] = make_float2(c1[2], c1[3]);
    }
    __syncthreads();

    // Phase 2: banded softmax (warp per query, strided by 12)
    for (int q = warp; q < 32; q += 12) {
        float sc0 = Ss[q * 100 + q + lane]      * 0.125f;
        float sc1 = Ss[q * 100 + q + lane + 32] * 0.125f;
        float m = fmaxf(sc0, sc1);
        #pragma unroll
        for (int o = 16; o; o >>= 1) m = fmaxf(m, __shfl_xor_sync(0xFFFFFFFFu, m, o));
        float e0 = __expf(sc0 - m);
        float e1 = __expf(sc1 - m);
        float sum = e0 + e1;
        #pragma unroll
        for (int o = 16; o; o >>= 1) sum += __shfl_xor_sync(0xFFFFFFFFu, sum, o);
        float inv = 1.f / sum;
        Ph[q * 104 + q + lane]      = __float2half(e0 * inv);
        Ph[q * 104 + q + lane + 32] = __float2half(e1 * inv);
    }
    __syncthreads();

    // Phase 3: ctx = P @ V^T. Warps 0..7 = 2M x 4N (m16 x n16), K=96 (6 steps).
    if (warp < 8) {
        const int wm = warp & 1;
        const int wn = warp >> 1;       // 0..3
        float c0[4] = {0.f, 0.f, 0.f, 0.f};
        float c1[4] = {0.f, 0.f, 0.f, 0.f};
        #pragma unroll
        for (int ks = 0; ks < 6; ks++) {
            const uint32_t colb = (uint32_t)ks * 32 + asel;
            uint32_t a[4], bf[4];
            ldsm4(a,  pb + ((uint32_t)(wm * 16) + arow) * 208 + colb);
            ldsm4(bf, vb + ((uint32_t)(wn * 16) + arow) * 208 + colb);
            mma_f16(c0, a, bf[0], bf[2]);
            mma_f16(c1, a, bf[1], bf[3]);
        }
        const int g  = lane >> 2;
        const int tg = lane & 3;
        const int q  = wm * 16 + g;
        const int d0 = wn * 16 + tg * 2;
        *(__half2*)&g_ch[base + (s0 + q) * HS + d0]         = __floats2half2_rn(c0[0], c0[1]);
        *(__half2*)&g_ch[base + (s0 + q + 8) * HS + d0]     = __floats2half2_rn(c0[2], c0[3]);
        *(__half2*)&g_ch[base + (s0 + q) * HS + d0 + 8]     = __floats2half2_rn(c1[0], c1[1]);
        *(__half2*)&g_ch[base + (s0 + q + 8) * HS + d0 + 8] = __floats2half2_rn(c1[2], c1[3]);
    }
}

// ---------------------------------------------------------------------------
extern "C" void kernel_launch(void* const* d_in, const int* in_sizes, int n_in,
                              void* d_out, int out_size)
{
    const float* X  = (const float*)d_in[0];
    const float* Wq = (const float*)d_in[1];
    const float* bq = (const float*)d_in[2];
    const float* Wk = (const float*)d_in[3];
    const float* bk = (const float*)d_in[4];
    const float* Wv = (const float*)d_in[5];
    const float* bv = (const float*)d_in[6];
    const float* Wo = (const float*)d_in[7];
    const float* bo = (const float*)d_in[8];
    float* out = (float*)d_out;

    static bool attr_done = false;
    if (!attr_done) {
        cudaFuncSetAttribute(qkv_kernel,  cudaFuncAttributeMaxDynamicSharedMemorySize, SMEM_QKV);
        cudaFuncSetAttribute(out_kernel,  cudaFuncAttributeMaxDynamicSharedMemorySize, SMEM_OUT);
        cudaFuncSetAttribute(attn_kernel, cudaFuncAttributeMaxDynamicSharedMemorySize, SMEM_ATTN);
        attr_done = true;
    }

    cvt_kernel<<<1024, 256>>>(X, Wq, Wk, Wv, Wo);

    dim3 qkv_grid(HS / 256, MTOK / 128, 3);    // (3, 16, 3) = 144 ~ one wave
    qkv_kernel<<<qkv_grid, 256, SMEM_QKV>>>(bq, bk, bv);

    dim3 attn_grid(SEQ / 32, NH, BATCH);       // (32, 12, 2) = 768
    attn_kernel<<<attn_grid, 384, SMEM_ATTN>>>();

    dim3 out_grid(HS / 96, MTOK / 64, 1);      // (8, 32) = 256, single wave
    out_kernel<<<out_grid, 192, SMEM_OUT>>>(bo, out);
}

// round 13
// speedup vs baseline: 2.5922x; 1.0667x over previous
#include <cuda_runtime.h>
#include <cuda_fp16.h>
#include <cstdint>

#define BATCH 2
#define SEQ   1024
#define HS    768
#define NH    12
#define HD    64
#define WIN   64
#define HALF  32
#define MTOK  (BATCH*SEQ)   // 2048
#define NX    (MTOK*HS)
#define NW    (HS*HS)
#define BK    64
#define NKC   (HS / BK)     // 12

// ---------------------------------------------------------------------------
// Device-global scratch
// ---------------------------------------------------------------------------
__device__ __half g_qh[NX], g_kh[NX], g_vh[NX];
__device__ __half g_xh[NX];
__device__ __half g_ch[NX];
__device__ __half g_wqh[NW], g_wkh[NW], g_wvh[NW], g_woh[NW];

// ---------------------------------------------------------------------------
// PTX helpers
// ---------------------------------------------------------------------------
__device__ __forceinline__ uint32_t smem_u32(const void* p) {
    uint32_t a;
    asm("{ .reg .u64 t; cvta.to.shared.u64 t, %1; cvt.u32.u64 %0, t; }" : "=r"(a) : "l"(p));
    return a;
}
__device__ __forceinline__ void cp16(uint32_t dst, const void* src) {
    asm volatile("cp.async.cg.shared.global [%0], [%1], 16;" :: "r"(dst), "l"(src));
}
#define CP_COMMIT() asm volatile("cp.async.commit_group;")
#define CP_WAIT0()  asm volatile("cp.async.wait_group 0;")
#define CP_WAIT1()  asm volatile("cp.async.wait_group 1;")

__device__ __forceinline__ void ldsm4(uint32_t* r, uint32_t addr) {
    asm volatile("ldmatrix.sync.aligned.m8n8.x4.shared.b16 {%0,%1,%2,%3}, [%4];"
        : "=r"(r[0]), "=r"(r[1]), "=r"(r[2]), "=r"(r[3]) : "r"(addr));
}
__device__ __forceinline__ void mma_f16(float* d, const uint32_t* a, uint32_t b0, uint32_t b1) {
    asm volatile(
        "mma.sync.aligned.m16n8k16.row.col.f32.f16.f16.f32 "
        "{%0,%1,%2,%3}, {%4,%5,%6,%7}, {%8,%9}, {%0,%1,%2,%3};"
        : "+f"(d[0]), "+f"(d[1]), "+f"(d[2]), "+f"(d[3])
        : "r"(a[0]), "r"(a[1]), "r"(a[2]), "r"(a[3]), "r"(b0), "r"(b1));
}

// ===========================================================================
// QKV GEMM (fp16): CTA 128x256, 8 warps (2M x 4N), warp 64x64, 1 CTA/SM.
// BK=64: row = 128B data padded to 144B stride (conflict-free: 8-row phase
// walks 0,16,..,112 mod 128).  Stage: A(128r)@0, B(256r)@18432 = 55296 B, 3 st.
// ===========================================================================
#define QSTG  55296
#define SMEM_QKV (3 * QSTG)

__device__ __forceinline__ void load_q(
    uint32_t sb, int st, int kc, const __half* __restrict__ W,
    int by, int bx, int tid)
{
    const int k0 = kc * BK;
    const uint32_t base = sb + (uint32_t)st * QSTG;
    #pragma unroll
    for (int it = 0; it < 12; it++) {
        int idx = it * 256 + tid;          // 0..3071
        int r   = idx >> 3;                // 0..383
        int cb  = idx & 7;
        const __half* src; uint32_t toff; int row;
        if (r < 128) { src = g_xh + (size_t)(by * 128 + r) * HS;         toff = 0;     row = r; }
        else         { src = W    + (size_t)(bx * 256 + (r - 128)) * HS; toff = 18432; row = r - 128; }
        cp16(base + toff + (uint32_t)row * 144 + (uint32_t)cb * 16, src + k0 + cb * 8);
    }
}

__global__ __launch_bounds__(256, 1) void qkv_kernel(
    const float* __restrict__ bq, const float* __restrict__ bk, const float* __restrict__ bv)
{
    const __half* W; const float* bias; __half* C;
    if (blockIdx.z == 0)      { W = g_wqh; bias = bq; C = g_qh; }
    else if (blockIdx.z == 1) { W = g_wkh; bias = bk; C = g_kh; }
    else                      { W = g_wvh; bias = bv; C = g_vh; }

    extern __shared__ char smem[];
    const uint32_t sb = smem_u32(smem);
    const int tid  = threadIdx.x;
    const int lane = tid & 31;
    const int warp = tid >> 5;
    const int wm   = warp & 1;
    const int wn   = warp >> 1;
    const int bx = blockIdx.x, by = blockIdx.y;

    float acc[4][8][4];
    #pragma unroll
    for (int i = 0; i < 4; i++)
        #pragma unroll
        for (int j = 0; j < 8; j++)
            #pragma unroll
            for (int r = 0; r < 4; r++) acc[i][j][r] = 0.f;

    load_q(sb, 0, 0, W, by, bx, tid); CP_COMMIT();
    load_q(sb, 1, 1, W, by, bx, tid); CP_COMMIT();

    const uint32_t arow = (uint32_t)(lane & 15);
    const uint32_t asel = (uint32_t)(lane >> 4) * 16;

    for (int kc = 0; kc < NKC; kc++) {
        if (kc + 1 < NKC) { CP_WAIT1(); } else { CP_WAIT0(); }
        __syncthreads();
        if (kc + 2 < NKC) {
            load_q(sb, (kc + 2) % 3, kc + 2, W, by, bx, tid);
            CP_COMMIT();
        }
        const uint32_t base = sb + (uint32_t)(kc % 3) * QSTG;

        #pragma unroll
        for (int ks = 0; ks < 4; ks++) {
            const uint32_t colb = (uint32_t)ks * 32 + asel;
            uint32_t ah[4][4];
            #pragma unroll
            for (int i = 0; i < 4; i++) {
                uint32_t ro = (uint32_t)(wm * 64 + i * 16) + arow;
                ldsm4(ah[i], base + ro * 144 + colb);
            }
            #pragma unroll
            for (int jj = 0; jj < 4; jj++) {
                uint32_t bf[4];
                uint32_t ro = (uint32_t)(wn * 64 + jj * 16) + arow;
                ldsm4(bf, base + 18432 + ro * 144 + colb);
                #pragma unroll
                for (int i = 0; i < 4; i++) {
                    mma_f16(acc[i][jj * 2 + 0], ah[i], bf[0], bf[2]);
                    mma_f16(acc[i][jj * 2 + 1], ah[i], bf[1], bf[3]);
                }
            }
        }
        // no trailing barrier: 3-stage rotation makes the kc+2 write WAR-safe
    }

    const int g  = lane >> 2;
    const int tg = lane & 3;
    #pragma unroll
    for (int i = 0; i < 4; i++) {
        const int row = by * 128 + wm * 64 + i * 16 + g;
        #pragma unroll
        for (int jj = 0; jj < 4; jj++) {
            #pragma unroll
            for (int s = 0; s < 2; s++) {
                const int col = bx * 256 + wn * 64 + jj * 16 + s * 8 + tg * 2;
                const float* a = acc[i][jj * 2 + s];
                const float b0 = bias[col], b1 = bias[col + 1];
                *(__half2*)&C[(size_t)row * HS + col]       = __floats2half2_rn(a[0] + b0, a[1] + b1);
                *(__half2*)&C[(size_t)(row + 8) * HS + col] = __floats2half2_rn(a[2] + b0, a[3] + b1);
            }
        }
    }
}

// ===========================================================================
// Output projection (fp16): CTA 64x96, 6 warps (2M x 3N), warp 32x32, 3/SM.
// BK=64, row stride 144B.  Stage: A(64r)@0, B(96r)@9216 = 23040 B, 3 stages.
// ===========================================================================
#define OSTG  23040
#define SMEM_OUT (3 * OSTG)

__device__ __forceinline__ void load_o(
    uint32_t sb, int st, int kc, int by, int bx, int tid)
{
    const int k0 = kc * BK;
    const uint32_t base = sb + (uint32_t)st * OSTG;
    #pragma unroll
    for (int it = 0; it < 7; it++) {
        int idx = it * 192 + tid;          // 0..1343, valid < 1280
        if (idx < 1280) {
            int r  = idx >> 3;             // 0..159
            int cb = idx & 7;
            const __half* src; uint32_t toff; int row;
            if (r < 64) { src = g_ch  + (size_t)(by * 64 + r) * HS;        toff = 0;    row = r; }
            else        { src = g_woh + (size_t)(bx * 96 + (r - 64)) * HS; toff = 9216; row = r - 64; }
            cp16(base + toff + (uint32_t)row * 144 + (uint32_t)cb * 16, src + k0 + cb * 8);
        }
    }
}

__global__ __launch_bounds__(192, 3) void out_kernel(
    const float* __restrict__ bo, float* __restrict__ Cout)
{
    extern __shared__ char smem[];
    const uint32_t sb = smem_u32(smem);
    const int tid  = threadIdx.x;
    const int lane = tid & 31;
    const int warp = tid >> 5;
    const int wm   = warp & 1;
    const int wn   = warp >> 1;
    const int bx = blockIdx.x, by = blockIdx.y;

    float acc[2][4][4];
    #pragma unroll
    for (int i = 0; i < 2; i++)
        #pragma unroll
        for (int j = 0; j < 4; j++)
            #pragma unroll
            for (int r = 0; r < 4; r++) acc[i][j][r] = 0.f;

    load_o(sb, 0, 0, by, bx, tid); CP_COMMIT();
    load_o(sb, 1, 1, by, bx, tid); CP_COMMIT();

    const uint32_t arow = (uint32_t)(lane & 15);
    const uint32_t asel = (uint32_t)(lane >> 4) * 16;

    for (int kc = 0; kc < NKC; kc++) {
        if (kc + 1 < NKC) { CP_WAIT1(); } else { CP_WAIT0(); }
        __syncthreads();
        if (kc + 2 < NKC) {
            load_o(sb, (kc + 2) % 3, kc + 2, by, bx, tid);
            CP_COMMIT();
        }
        const uint32_t base = sb + (uint32_t)(kc % 3) * OSTG;

        #pragma unroll
        for (int ks = 0; ks < 4; ks++) {
            const uint32_t colb = (uint32_t)ks * 32 + asel;
            uint32_t ah[2][4];
            #pragma unroll
            for (int i = 0; i < 2; i++) {
                uint32_t ro = (uint32_t)(wm * 32 + i * 16) + arow;
                ldsm4(ah[i], base + ro * 144 + colb);
            }
            #pragma unroll
            for (int jj = 0; jj < 2; jj++) {
                uint32_t bf[4];
                uint32_t ro = (uint32_t)(wn * 32 + jj * 16) + arow;
                ldsm4(bf, base + 9216 + ro * 144 + colb);
                #pragma unroll
                for (int i = 0; i < 2; i++) {
                    mma_f16(acc[i][jj * 2 + 0], ah[i], bf[0], bf[2]);
                    mma_f16(acc[i][jj * 2 + 1], ah[i], bf[1], bf[3]);
                }
            }
        }
        // no trailing barrier (3-stage WAR-safe)
    }

    const int g  = lane >> 2;
    const int tg = lane & 3;
    #pragma unroll
    for (int i = 0; i < 2; i++) {
        const int row = by * 64 + wm * 32 + i * 16 + g;
        #pragma unroll
        for (int j = 0; j < 4; j++) {
            const int col = bx * 96 + wn * 32 + (j >> 1) * 16 + (j & 1) * 8 + tg * 2;
            const float b0 = bo[col], b1 = bo[col + 1];
            *(float2*)&Cout[(size_t)row * HS + col] =
                make_float2(acc[i][j][0] + b0, acc[i][j][1] + b1);
            *(float2*)&Cout[(size_t)(row + 8) * HS + col] =
                make_float2(acc[i][j][2] + b0, acc[i][j][3] + b1);
        }
    }
}

// ---------------------------------------------------------------------------
// Convert fp32 -> fp16 (X + 4 weights).
// ---------------------------------------------------------------------------
__global__ void cvt_kernel(
    const float* __restrict__ X,
    const float* __restrict__ Wq, const float* __restrict__ Wk,
    const float* __restrict__ Wv, const float* __restrict__ Wo)
{
    const int tot4 = (NX + 4 * NW) / 4;
    for (int i4 = blockIdx.x * blockDim.x + threadIdx.x; i4 < tot4; i4 += gridDim.x * blockDim.x) {
        int i = i4 * 4;
        const float* src; __half* dst; int r;
        if (i < NX) { src = X; dst = g_xh; r = i; }
        else {
            int j = i - NX; int w = j / NW; r = j - w * NW;
            if (w == 0)      { src = Wq; dst = g_wqh; }
            else if (w == 1) { src = Wk; dst = g_wkh; }
            else if (w == 2) { src = Wv; dst = g_wvh; }
            else             { src = Wo; dst = g_woh; }
        }
        float4 x = *(const float4*)(src + r);
        *(__half2*)(dst + r)     = __floats2half2_rn(x.x, x.y);
        *(__half2*)(dst + r + 2) = __floats2half2_rn(x.z, x.w);
    }
}

// ===========================================================================
// Sliding-window attention via HMMA (proven R12 version).
// ===========================================================================
#define SMEM_ATTN 51200

__global__ __launch_bounds__(384) void attn_kernel()
{
    extern __shared__ char smc[];
    const uint32_t sb = smem_u32(smc);
    __half* Qh = (__half*)smc;              // stride 72 halfs (144B)
    __half* Kh = (__half*)(smc + 4608);     // stride 72
    __half* Vt = (__half*)(smc + 18432);    // stride 104 halfs (208B)
    float*  Ss = (float*)(smc + 31744);     // stride 100 floats (400B)
    __half* Ph = (__half*)(smc + 44544);    // stride 104

    const int s0 = blockIdx.x * 32;
    const int h  = blockIdx.y;
    const int b  = blockIdx.z;
    const int tid = threadIdx.x;
    const int base = (b * SEQ) * HS + h * HD;

    for (int i = tid; i < 256; i += 384) {
        int r = i >> 3, c = i & 7;
        *(uint4*)&Qh[r * 72 + c * 8] = *(const uint4*)&g_qh[base + (s0 + r) * HS + c * 8];
    }
    for (int i = tid; i < 768; i += 384) {
        int r = i >> 3, c = i & 7;
        int j = s0 - HALF + r;
        uint4 v = make_uint4(0u, 0u, 0u, 0u);
        if (r < 95 && j >= 0 && j < SEQ) v = *(const uint4*)&g_kh[base + j * HS + c * 8];
        *(uint4*)&Kh[r * 72 + c * 8] = v;
    }
    for (int i = tid; i < 768; i += 384) {
        int r = i >> 3, c = i & 7;
        int j = s0 - HALF + r;
        __half hv[8];
        uint4 v = make_uint4(0u, 0u, 0u, 0u);
        if (r < 95 && j >= 0 && j < SEQ) v = *(const uint4*)&g_vh[base + j * HS + c * 8];
        *(uint4*)hv = v;
        #pragma unroll
        for (int t = 0; t < 8; t++) Vt[(c * 8 + t) * 104 + r] = hv[t];
    }
    for (int i = tid; i < 1664; i += 384) ((uint32_t*)Ph)[i] = 0u;
    __syncthreads();

    const int lane = tid & 31;
    const int warp = tid >> 5;
    const uint32_t arow = (uint32_t)(lane & 15);
    const uint32_t asel = (uint32_t)(lane >> 4) * 16;
    const uint32_t qb = sb;
    const uint32_t kb = sb + 4608;
    const uint32_t vb = sb + 18432;
    const uint32_t pb = sb + 44544;

    {
        const int wm = warp & 1;
        const int wn = warp >> 1;       // 0..5
        float c0[4] = {0.f, 0.f, 0.f, 0.f};
        float c1[4] = {0.f, 0.f, 0.f, 0.f};
        #pragma unroll
        for (int ks = 0; ks < 4; ks++) {
            const uint32_t colb = (uint32_t)ks * 32 + asel;
            uint32_t a[4], bf[4];
            ldsm4(a,  qb + ((uint32_t)(wm * 16) + arow) * 144 + colb);
            ldsm4(bf, kb + ((uint32_t)(wn * 16) + arow) * 144 + colb);
            mma_f16(c0, a, bf[0], bf[2]);
            mma_f16(c1, a, bf[1], bf[3]);
        }
        const int g  = lane >> 2;
        const int tg = lane & 3;
        const int row = wm * 16 + g;
        const int col = wn * 16 + tg * 2;
        *(float2*)&Ss[row * 100 + col]           = make_float2(c0[0], c0[1]);
        *(float2*)&Ss[(row + 8) * 100 + col]     = make_float2(c0[2], c0[3]);
        *(float2*)&Ss[row * 100 + col + 8]       = make_float2(c1[0], c1[1]);
        *(float2*)&Ss[(row + 8) * 100 + col + 8] = make_float2(c1[2], c1[3]);
    }
    __syncthreads();

    for (int q = warp; q < 32; q += 12) {
        float sc0 = Ss[q * 100 + q + lane]      * 0.125f;
        float sc1 = Ss[q * 100 + q + lane + 32] * 0.125f;
        float m = fmaxf(sc0, sc1);
        #pragma unroll
        for (int o = 16; o; o >>= 1) m = fmaxf(m, __shfl_xor_sync(0xFFFFFFFFu, m, o));
        float e0 = __expf(sc0 - m);
        float e1 = __expf(sc1 - m);
        float sum = e0 + e1;
        #pragma unroll
        for (int o = 16; o; o >>= 1) sum += __shfl_xor_sync(0xFFFFFFFFu, sum, o);
        float inv = 1.f / sum;
        Ph[q * 104 + q + lane]      = __float2half(e0 * inv);
        Ph[q * 104 + q + lane + 32] = __float2half(e1 * inv);
    }
    __syncthreads();

    if (warp < 8) {
        const int wm = warp & 1;
        const int wn = warp >> 1;       // 0..3
        float c0[4] = {0.f, 0.f, 0.f, 0.f};
        float c1[4] = {0.f, 0.f, 0.f, 0.f};
        #pragma unroll
        for (int ks = 0; ks < 6; ks++) {
            const uint32_t colb = (uint32_t)ks * 32 + asel;
            uint32_t a[4], bf[4];
            ldsm4(a,  pb + ((uint32_t)(wm * 16) + arow) * 208 + colb);
            ldsm4(bf, vb + ((uint32_t)(wn * 16) + arow) * 208 + colb);
            mma_f16(c0, a, bf[0], bf[2]);
            mma_f16(c1, a, bf[1], bf[3]);
        }
        const int g  = lane >> 2;
        const int tg = lane & 3;
        const int q  = wm * 16 + g;
        const int d0 = wn * 16 + tg * 2;
        *(__half2*)&g_ch[base + (s0 + q) * HS + d0]         = __floats2half2_rn(c0[0], c0[1]);
        *(__half2*)&g_ch[base + (s0 + q + 8) * HS + d0]     = __floats2half2_rn(c0[2], c0[3]);
        *(__half2*)&g_ch[base + (s0 + q) * HS + d0 + 8]     = __floats2half2_rn(c1[0], c1[1]);
        *(__half2*)&g_ch[base + (s0 + q + 8) * HS + d0 + 8] = __floats2half2_rn(c1[2], c1[3]);
    }
}

// ---------------------------------------------------------------------------
extern "C" void kernel_launch(void* const* d_in, const int* in_sizes, int n_in,
                              void* d_out, int out_size)
{
    const float* X  = (const float*)d_in[0];
    const float* Wq = (const float*)d_in[1];
    const float* bq = (const float*)d_in[2];
    const float* Wk = (const float*)d_in[3];
    const float* bk = (const float*)d_in[4];
    const float* Wv = (const float*)d_in[5];
    const float* bv = (const float*)d_in[6];
    const float* Wo = (const float*)d_in[7];
    const float* bo = (const float*)d_in[8];
    float* out = (float*)d_out;

    static bool attr_done = false;
    if (!attr_done) {
        cudaFuncSetAttribute(qkv_kernel,  cudaFuncAttributeMaxDynamicSharedMemorySize, SMEM_QKV);
        cudaFuncSetAttribute(out_kernel,  cudaFuncAttributeMaxDynamicSharedMemorySize, SMEM_OUT);
        cudaFuncSetAttribute(attn_kernel, cudaFuncAttributeMaxDynamicSharedMemorySize, SMEM_ATTN);
        attr_done = true;
    }

    cvt_kernel<<<1024, 256>>>(X, Wq, Wk, Wv, Wo);

    dim3 qkv_grid(HS / 256, MTOK / 128, 3);    // (3, 16, 3) = 144 ~ one wave
    qkv_kernel<<<qkv_grid, 256, SMEM_QKV>>>(bq, bk, bv);

    dim3 attn_grid(SEQ / 32, NH, BATCH);       // (32, 12, 2) = 768
    attn_kernel<<<attn_grid, 384, SMEM_ATTN>>>();

    dim3 out_grid(HS / 96, MTOK / 64, 1);      // (8, 32) = 256, single wave
    out_kernel<<<out_grid, 192, SMEM_OUT>>>(bo, out);
}